// round 1
// baseline (speedup 1.0000x reference)
#include <cuda_runtime.h>
#include <math.h>

#define GN 20000
#define GE 320000
// C=64, F=128, NUM_REL=2

// ---------------- scratch (static device globals; no runtime alloc) ----------
__device__ float g_W0[128 * 384];
__device__ float g_B0[384];
__device__ float g_W1[64 * 384];
__device__ float g_B1[384];
__device__ float g_OUT0[(size_t)GN * 384]; // layer0: [hp | mp0 | mp1 | he | me0 | me1]
__device__ float g_OUT1[(size_t)GN * 384]; // layer1: same layout
__device__ float g_P[(size_t)GN * 64];     // log_softmax(s)
__device__ float g_XE[(size_t)GN * 64];    // relu'd g1e output
__device__ float g_M[(size_t)GN * 128];    // coarsen scatter: [M0 | M1]
__device__ float g_CO[64 * 192];           // P^T @ [M0 | M1 | XE]  = [A0 | A1 | x1]

// ---------------- weight packing --------------------------------------------
__global__ void pack_weights(const float* __restrict__ pws0, const float* __restrict__ pwr0,
                             const float* __restrict__ pws1, const float* __restrict__ pwr1,
                             const float* __restrict__ pb,
                             const float* __restrict__ ews0, const float* __restrict__ ewr0,
                             const float* __restrict__ ews1, const float* __restrict__ ewr1,
                             const float* __restrict__ eb)
{
    int i = blockIdx.x * 256 + threadIdx.x;
    if (i < 128 * 384) {
        int k = i / 384, j = i % 384;
        int g = j >> 6, c = j & 63;
        float v;
        switch (g) {
            case 0: v = pws0[k * 64 + c]; break;
            case 1: v = pwr0[k * 64 + c]; break;
            case 2: v = pwr0[8192 + k * 64 + c]; break;
            case 3: v = ews0[k * 64 + c]; break;
            case 4: v = ewr0[k * 64 + c]; break;
            default: v = ewr0[8192 + k * 64 + c]; break;
        }
        g_W0[i] = v;
    }
    if (i < 64 * 384) {
        int k = i / 384, j = i % 384;
        int g = j >> 6, c = j & 63;
        float v;
        switch (g) {
            case 0: v = pws1[k * 64 + c]; break;
            case 1: v = pwr1[k * 64 + c]; break;
            case 2: v = pwr1[4096 + k * 64 + c]; break;
            case 3: v = ews1[k * 64 + c]; break;
            case 4: v = ewr1[k * 64 + c]; break;
            default: v = ewr1[4096 + k * 64 + c]; break;
        }
        g_W1[i] = v;
    }
    if (i < 384) {
        int g = i >> 6, c = i & 63;
        g_B0[i] = (g == 0) ? pb[c] : (g == 3 ? eb[c] : 0.f);
        g_B1[i] = (g == 0) ? pb[64 + c] : (g == 3 ? eb[64 + c] : 0.f);
    }
}

// ---------------- zero scratch ----------------------------------------------
__global__ void zero_kernel()
{
    const int total = GN * 128 + 64 * 192;
    for (int i = blockIdx.x * 256 + threadIdx.x; i < total; i += gridDim.x * 256) {
        if (i < GN * 128) g_M[i] = 0.f;
        else g_CO[i - GN * 128] = 0.f;
    }
}

// ---------------- big GEMM (M x K @ K x 384) --------------------------------
__device__ __forceinline__ void gemm_body(const float* __restrict__ A, int lda, int aGroupStride,
                                          const float* __restrict__ W, const float* __restrict__ bias,
                                          float* __restrict__ C, int K)
{
    __shared__ float As[64][36];
    __shared__ float Bs[32][64];
    int tid = threadIdx.x;
    int m0 = blockIdx.x * 64;
    int n0 = blockIdx.y * 64;
    const float* Ab = A + (n0 / 192) * aGroupStride;
    int tx = tid & 15, ty = tid >> 4;
    float acc[4][4] = {};
    for (int kk = 0; kk < K; kk += 32) {
#pragma unroll
        for (int l = 0; l < 2; l++) {
            int f = tid + l * 256;
            int r = f >> 3, c4 = (f & 7) << 2;
            int gm = m0 + r;
            float4 v = make_float4(0.f, 0.f, 0.f, 0.f);
            if (gm < GN) v = *(const float4*)(Ab + (size_t)gm * lda + kk + c4);
            *(float4*)&As[r][c4] = v;
        }
#pragma unroll
        for (int l = 0; l < 2; l++) {
            int f = tid + l * 256;
            int r = f >> 4, c4 = (f & 15) << 2;
            *(float4*)&Bs[r][c4] = *(const float4*)(W + (size_t)(kk + r) * 384 + n0 + c4);
        }
        __syncthreads();
#pragma unroll
        for (int k = 0; k < 32; k++) {
            float a0 = As[ty * 4 + 0][k];
            float a1 = As[ty * 4 + 1][k];
            float a2 = As[ty * 4 + 2][k];
            float a3 = As[ty * 4 + 3][k];
            float4 bv = *(float4*)&Bs[k][tx * 4];
            acc[0][0] += a0 * bv.x; acc[0][1] += a0 * bv.y; acc[0][2] += a0 * bv.z; acc[0][3] += a0 * bv.w;
            acc[1][0] += a1 * bv.x; acc[1][1] += a1 * bv.y; acc[1][2] += a1 * bv.z; acc[1][3] += a1 * bv.w;
            acc[2][0] += a2 * bv.x; acc[2][1] += a2 * bv.y; acc[2][2] += a2 * bv.z; acc[2][3] += a2 * bv.w;
            acc[3][0] += a3 * bv.x; acc[3][1] += a3 * bv.y; acc[3][2] += a3 * bv.z; acc[3][3] += a3 * bv.w;
        }
        __syncthreads();
    }
#pragma unroll
    for (int i = 0; i < 4; i++) {
        int gm = m0 + ty * 4 + i;
        if (gm >= GN) continue;
#pragma unroll
        for (int j = 0; j < 4; j++)
            C[(size_t)gm * 384 + n0 + tx * 4 + j] = acc[i][j] + bias[n0 + tx * 4 + j];
    }
}

__global__ void gemm0_kernel(const float* __restrict__ x) { gemm_body(x, 128, 0, g_W0, g_B0, g_OUT0, 128); }
__global__ void gemm1_kernel() { gemm_body(g_OUT0, 384, 192, g_W1, g_B1, g_OUT1, 64); }

// ---------------- edge scatter (segment sums) -------------------------------
// one warp per edge; lanes 0-15 = pair1, lanes 16-31 = pair2
// mode 0: layer0 on g_OUT0 ; mode 1: layer1 on g_OUT1 ; mode 2: coarsen P -> g_M
__global__ void scatter_kernel(const int* __restrict__ e1, const float* __restrict__ a1,
                               const int* __restrict__ e2, const float* __restrict__ a2,
                               int rel, int mode)
{
    int warp = blockIdx.x * (blockDim.x >> 5) + (threadIdx.x >> 5);
    if (warp >= GE) return;
    int lane = threadIdx.x & 31;
    bool second = lane >= 16;
    int l = lane & 15;
    const int* e = second ? e2 : e1;
    const float* at = second ? a2 : a1;
    int dst = e[warp];
    int src = e[GE + warp];
    float a = at[warp];
    const float* rbuf;
    float* wbuf;
    int rs, ws, ro, wo;
    if (mode == 2) {
        rbuf = g_P; rs = 64; ro = 0;
        wbuf = g_M; ws = 128; wo = second ? 64 : 0;
    } else {
        float* b = mode ? g_OUT1 : g_OUT0;
        rbuf = b; wbuf = b; rs = 384; ws = 384;
        ro = (second ? 256 : 64) + rel * 64;
        wo = second ? 192 : 0;
    }
    float4 v = *(const float4*)(rbuf + (size_t)src * rs + ro + l * 4);
    float* w = wbuf + (size_t)dst * ws + wo + l * 4;
    atomicAdd(w + 0, a * v.x);
    atomicAdd(w + 1, a * v.y);
    atomicAdd(w + 2, a * v.z);
    atomicAdd(w + 3, a * v.w);
}

// ---------------- relu on layer0 self-columns (in place) --------------------
__global__ void relu0_kernel()
{
    int i = blockIdx.x * 256 + threadIdx.x;
    if (i >= GN * 128) return;
    int n = i >> 7, c = i & 127;
    int col = (c < 64) ? c : (128 + c); // 192 + (c-64)
    float* p = g_OUT0 + (size_t)n * 384 + col;
    *p = fmaxf(*p, 0.f);
}

// ---------------- relu + write s + log_softmax P + XE -----------------------
__global__ void finalize_sparse(float* __restrict__ dout, int full)
{
    int row = blockIdx.x * 8 + (threadIdx.x >> 5);
    if (row >= GN) return;
    int lane = threadIdx.x & 31;
    const float* rp = g_OUT1 + (size_t)row * 384;
    float s0 = fmaxf(rp[lane], 0.f);
    float s1 = fmaxf(rp[lane + 32], 0.f);
    float e0 = fmaxf(rp[192 + lane], 0.f);
    float e1 = fmaxf(rp[224 + lane], 0.f);
    if (full) {
        dout[32 + (size_t)row * 64 + lane] = s0;
        dout[32 + (size_t)row * 64 + 32 + lane] = s1;
    }
    g_XE[(size_t)row * 64 + lane] = e0;
    g_XE[(size_t)row * 64 + 32 + lane] = e1;
    float m = fmaxf(s0, s1);
#pragma unroll
    for (int off = 16; off; off >>= 1) m = fmaxf(m, __shfl_xor_sync(0xffffffffu, m, off));
    float sum = expf(s0 - m) + expf(s1 - m);
#pragma unroll
    for (int off = 16; off; off >>= 1) sum += __shfl_xor_sync(0xffffffffu, sum, off);
    float lse = m + logf(sum);
    g_P[(size_t)row * 64 + lane] = s0 - lse;
    g_P[(size_t)row * 64 + 32 + lane] = s1 - lse;
}

// ---------------- P^T @ [M0 | M1 | XE]  ->  g_CO [64 x 192] -----------------
__global__ void ptgemm_kernel()
{
    __shared__ float Ps[64];
    __shared__ float Bsr[192];
    int tid = threadIdx.x;
    int ag = tid & 15;  // a-rows ag*4 .. +3
    int bg = tid >> 4;  // b-cols bg*12 .. +11
    float acc[4][12] = {};
    int rpb = (GN + gridDim.x - 1) / gridDim.x;
    int r0 = blockIdx.x * rpb;
    int r1 = min(GN, r0 + rpb);
    for (int n = r0; n < r1; n++) {
        __syncthreads();
        if (tid < 64) Ps[tid] = g_P[(size_t)n * 64 + tid];
        else if (tid < 192) Bsr[tid - 64] = g_M[(size_t)n * 128 + tid - 64];
        else Bsr[tid - 64] = g_XE[(size_t)n * 64 + tid - 192];
        __syncthreads();
        float a[4];
#pragma unroll
        for (int i = 0; i < 4; i++) a[i] = Ps[ag * 4 + i];
        float b[12];
#pragma unroll
        for (int j = 0; j < 12; j++) b[j] = Bsr[bg * 12 + j];
#pragma unroll
        for (int i = 0; i < 4; i++)
#pragma unroll
            for (int j = 0; j < 12; j++) acc[i][j] += a[i] * b[j];
    }
#pragma unroll
    for (int i = 0; i < 4; i++)
#pragma unroll
        for (int j = 0; j < 12; j++)
            atomicAdd(&g_CO[(ag * 4 + i) * 192 + bg * 12 + j], acc[i][j]);
}

// ---------------- dense 64x64 GNN + head ------------------------------------
#define DSTR 68

template <bool ACC, bool BSMEM>
__device__ __forceinline__ void dmm(float* Cs, const float* As, const float* B,
                                    const float* bias, int tid)
{
    int r0 = (tid >> 4) << 2, c0 = (tid & 15) << 2;
    float acc[4][4];
#pragma unroll
    for (int i = 0; i < 4; i++)
#pragma unroll
        for (int j = 0; j < 4; j++)
            acc[i][j] = ACC ? Cs[(r0 + i) * DSTR + c0 + j] : (bias ? bias[c0 + j] : 0.f);
#pragma unroll 8
    for (int k = 0; k < 64; k++) {
        float a[4];
#pragma unroll
        for (int i = 0; i < 4; i++) a[i] = As[(r0 + i) * DSTR + k];
        float4 bv;
        if (BSMEM) bv = *(const float4*)(B + k * DSTR + c0);
        else bv = *(const float4*)(B + k * 64 + c0);
#pragma unroll
        for (int i = 0; i < 4; i++) {
            acc[i][0] += a[i] * bv.x;
            acc[i][1] += a[i] * bv.y;
            acc[i][2] += a[i] * bv.z;
            acc[i][3] += a[i] * bv.w;
        }
    }
#pragma unroll
    for (int i = 0; i < 4; i++)
#pragma unroll
        for (int j = 0; j < 4; j++)
            Cs[(r0 + i) * DSTR + c0 + j] = acc[i][j];
}

__global__ void dense_final(const float* __restrict__ Wself0, const float* __restrict__ Wrel0,
                            const float* __restrict__ Wself1, const float* __restrict__ Wrel1,
                            const float* __restrict__ gb,
                            const float* __restrict__ lin1W, const float* __restrict__ lin1b,
                            const float* __restrict__ lin2W, const float* __restrict__ lin2b,
                            float* __restrict__ dout, int full)
{
    extern __shared__ float sm[];
    float* X = sm;
    float* A0 = X + 64 * DSTR;
    float* A1 = A0 + 64 * DSTR;
    float* H = A1 + 64 * DSTR;
    float* H2 = H + 64 * DSTR;
    float* T = H2 + 64 * DSTR;
    int tid = threadIdx.x;
    int r0 = (tid >> 4) << 2, c0 = (tid & 15) << 2;
#pragma unroll
    for (int i = 0; i < 4; i++)
#pragma unroll
        for (int j = 0; j < 4; j++) {
            int r = r0 + i, c = c0 + j;
            float xv = g_CO[r * 192 + 128 + c];
            X[r * DSTR + c] = xv;
            if (full) dout[32 + (size_t)GN * 64 + r * 64 + c] = xv;
            A0[r * DSTR + c] = g_CO[r * 192 + c];
            A1[r * DSTR + c] = g_CO[r * 192 + 64 + c];
        }
    __syncthreads();
    dmm<false, false>(H, X, Wself0, gb, tid);          // H = X@Ws0 + b0
    dmm<false, false>(T, X, Wrel0, nullptr, tid);      // T = X@Wr0[0]
    __syncthreads();
    dmm<true, true>(H, A0, T, nullptr, tid);           // H += A0@T
    __syncthreads();
    dmm<false, false>(T, X, Wrel0 + 4096, nullptr, tid);
    __syncthreads();
    dmm<true, true>(H, A1, T, nullptr, tid);
#pragma unroll
    for (int i = 0; i < 4; i++)
#pragma unroll
        for (int j = 0; j < 4; j++) {
            float* p = &H[(r0 + i) * DSTR + c0 + j];
            *p = fmaxf(*p, 0.f);
        }
    __syncthreads();
    dmm<false, false>(H2, H, Wself1, gb + 64, tid);    // H2 = H@Ws1 + b1
    dmm<false, false>(T, H, Wrel1, nullptr, tid);
    __syncthreads();
    dmm<true, true>(H2, A0, T, nullptr, tid);
    __syncthreads();
    dmm<false, false>(T, H, Wrel1 + 4096, nullptr, tid);
    __syncthreads();
    dmm<true, true>(H2, A1, T, nullptr, tid);
#pragma unroll
    for (int i = 0; i < 4; i++)
#pragma unroll
        for (int j = 0; j < 4; j++) {
            float* p = &H2[(r0 + i) * DSTR + c0 + j];
            *p = fmaxf(*p, 0.f);
        }
    __syncthreads();
    if (tid < 64) {
        float s = 0.f;
        for (int r = 0; r < 64; r++) s += H2[r * DSTR + tid];
        T[tid] = s * (1.f / 64.f); // pooled mean over rows
    }
    __syncthreads();
    if (tid < 32) {
        float h1 = lin1b[tid];
        for (int c = 0; c < 64; c++) h1 += T[c] * lin1W[c * 32 + tid];
        h1 = (h1 > 0.f) ? h1 : 0.01f * h1; // leaky_relu
        T[64 + tid] = h1;
        __syncwarp();
        float lg = lin2b[tid];
        for (int j = 0; j < 32; j++) lg += T[64 + j] * lin2W[j * 32 + tid];
        float m = lg;
#pragma unroll
        for (int off = 16; off; off >>= 1) m = fmaxf(m, __shfl_xor_sync(0xffffffffu, m, off));
        float se = expf(lg - m);
#pragma unroll
        for (int off = 16; off; off >>= 1) se += __shfl_xor_sync(0xffffffffu, se, off);
        dout[tid] = lg - m - logf(se);
    }
}

// ---------------- launcher ---------------------------------------------------
extern "C" void kernel_launch(void* const* d_in, const int* in_sizes, int n_in,
                              void* d_out, int out_size)
{
    const float* x = (const float*)d_in[0];
    // resolve edge/attr ordering by sizes (dict order vs signature order)
    int iE0 = 1, iA0 = 2, iE1 = 3, iA1 = 4;
    if (in_sizes[2] == 2 * GE) { iE0 = 1; iE1 = 2; iA0 = 3; iA1 = 4; }
    const int* e0 = (const int*)d_in[iE0];
    const float* a0 = (const float*)d_in[iA0];
    const int* e1 = (const int*)d_in[iE1];
    const float* a1 = (const float*)d_in[iA1];
    const float* W[19];
    for (int i = 0; i < 19; i++) W[i] = (const float*)d_in[5 + i];
    // W[0..4]=g1p(ws0,wr0,ws1,wr1,b) W[5..9]=g1e W[10..14]=g2 W[15..18]=lin1W,lin1b,lin2W,lin2b
    int full = (out_size >= 32 + GN * 64 + 64 * 64) ? 1 : 0;
    float* dout = (float*)d_out;

    cudaFuncSetAttribute(dense_final, cudaFuncAttributeMaxDynamicSharedMemorySize,
                         6 * 64 * DSTR * (int)sizeof(float));

    pack_weights<<<192, 256>>>(W[0], W[1], W[2], W[3], W[4], W[5], W[6], W[7], W[8], W[9]);
    zero_kernel<<<2048, 256>>>();
    gemm0_kernel<<<dim3(313, 6), 256>>>(x);
    scatter_kernel<<<40000, 256>>>(e0, a0, e0, a0, 0, 0);
    scatter_kernel<<<40000, 256>>>(e1, a1, e1, a1, 1, 0);
    relu0_kernel<<<10000, 256>>>();
    gemm1_kernel<<<dim3(313, 6), 256>>>();
    scatter_kernel<<<40000, 256>>>(e0, a0, e0, a0, 0, 1);
    scatter_kernel<<<40000, 256>>>(e1, a1, e1, a1, 1, 1);
    finalize_sparse<<<2500, 256>>>(dout, full);
    scatter_kernel<<<40000, 256>>>(e0, a0, e1, a1, 0, 2);
    ptgemm_kernel<<<160, 256>>>();
    dense_final<<<1, 256, 6 * 64 * DSTR * sizeof(float)>>>(
        W[10], W[11], W[12], W[13], W[14], W[15], W[16], W[17], W[18], dout, full);
}

// round 2
// speedup vs baseline: 1.9508x; 1.9508x over previous
#include <cuda_runtime.h>
#include <math.h>

#define GN 20000
#define GE 320000
// C=64, F=128, NUM_REL=2

// ---------------- scratch (static device globals; no runtime alloc) ----------
__device__ float g_W0[128 * 384];
__device__ float g_B0[384];
__device__ float g_W1[64 * 384];
__device__ float g_B1[384];
__device__ float g_OUT0[(size_t)GN * 384]; // layer0: [hp | mp0 | mp1 | he | me0 | me1]
__device__ float g_OUT1[(size_t)GN * 384]; // layer1: same layout
__device__ float g_P[(size_t)GN * 64];     // log_softmax(s)
__device__ float g_XE[(size_t)GN * 64];    // relu'd g1e output
__device__ float g_M[(size_t)GN * 128];    // coarsen gather: [M0 | M1]
__device__ float g_CO[64 * 192];           // P^T @ [M0 | M1 | XE]  = [A0 | A1 | x1]

// CSR scratch
__device__ int   g_deg[2][GN];
__device__ int   g_off[2][GN + 1];
__device__ int   g_cur[2][GN];
__device__ int   g_esrc[2][GE];
__device__ float g_eattr[2][GE];

// ---------------- weight packing --------------------------------------------
__global__ void pack_weights(const float* __restrict__ pws0, const float* __restrict__ pwr0,
                             const float* __restrict__ pws1, const float* __restrict__ pwr1,
                             const float* __restrict__ pb,
                             const float* __restrict__ ews0, const float* __restrict__ ewr0,
                             const float* __restrict__ ews1, const float* __restrict__ ewr1,
                             const float* __restrict__ eb)
{
    int i = blockIdx.x * 256 + threadIdx.x;
    if (i < 128 * 384) {
        int k = i / 384, j = i % 384;
        int g = j >> 6, c = j & 63;
        float v;
        switch (g) {
            case 0: v = pws0[k * 64 + c]; break;
            case 1: v = pwr0[k * 64 + c]; break;
            case 2: v = pwr0[8192 + k * 64 + c]; break;
            case 3: v = ews0[k * 64 + c]; break;
            case 4: v = ewr0[k * 64 + c]; break;
            default: v = ewr0[8192 + k * 64 + c]; break;
        }
        g_W0[i] = v;
    }
    if (i < 64 * 384) {
        int k = i / 384, j = i % 384;
        int g = j >> 6, c = j & 63;
        float v;
        switch (g) {
            case 0: v = pws1[k * 64 + c]; break;
            case 1: v = pwr1[k * 64 + c]; break;
            case 2: v = pwr1[4096 + k * 64 + c]; break;
            case 3: v = ews1[k * 64 + c]; break;
            case 4: v = ewr1[k * 64 + c]; break;
            default: v = ewr1[4096 + k * 64 + c]; break;
        }
        g_W1[i] = v;
    }
    if (i < 384) {
        int g = i >> 6, c = i & 63;
        g_B0[i] = (g == 0) ? pb[c] : (g == 3 ? eb[c] : 0.f);
        g_B1[i] = (g == 0) ? pb[64 + c] : (g == 3 ? eb[64 + c] : 0.f);
    }
}

// ---------------- zero small scratch (degree counters + g_CO) ----------------
__global__ void zero_small()
{
    int i = blockIdx.x * 256 + threadIdx.x;
    if (i < 2 * GN) ((int*)g_deg)[i] = 0;
    else if (i < 2 * GN + 64 * 192) g_CO[i - 2 * GN] = 0.f;
}

// ---------------- CSR build: histogram -> scan -> place ----------------------
__global__ void hist_kernel(const int* __restrict__ e0, const int* __restrict__ e1)
{
    int i = blockIdx.x * 256 + threadIdx.x;
    if (i < GE) atomicAdd(&g_deg[0][e0[i]], 1);
    else if (i < 2 * GE) atomicAdd(&g_deg[1][e1[i - GE]], 1);
}

__global__ void scan_kernel()
{
    __shared__ int s[1024];
    int r = blockIdx.x;
    int t = threadIdx.x;
    int carry = 0;
    for (int base = 0; base < GN; base += 1024) {
        int v = (base + t < GN) ? g_deg[r][base + t] : 0;
        s[t] = v;
        __syncthreads();
        for (int o = 1; o < 1024; o <<= 1) {
            int x = (t >= o) ? s[t - o] : 0;
            __syncthreads();
            s[t] += x;
            __syncthreads();
        }
        if (base + t < GN) {
            int ex = carry + s[t] - v;
            g_off[r][base + t] = ex;
            g_cur[r][base + t] = ex;
        }
        int tot = s[1023];
        __syncthreads();
        carry += tot;
    }
    if (t == 0) g_off[r][GN] = carry;
}

__global__ void place_kernel(const int* __restrict__ e0, const float* __restrict__ a0,
                             const int* __restrict__ e1, const float* __restrict__ a1)
{
    int i = blockIdx.x * 256 + threadIdx.x;
    int r, j;
    const int* e;
    const float* at;
    if (i < GE) { r = 0; j = i; e = e0; at = a0; }
    else if (i < 2 * GE) { r = 1; j = i - GE; e = e1; at = a1; }
    else return;
    int dst = e[j];
    int src = e[GE + j];
    float a = at[j];
    int pos = atomicAdd(&g_cur[r][dst], 1);
    g_esrc[r][pos] = src;
    g_eattr[r][pos] = a;
}

// ---------------- big GEMM (M x K @ K x 384) --------------------------------
__device__ __forceinline__ void gemm_body(const float* __restrict__ A, int lda, int aGroupStride,
                                          const float* __restrict__ W, const float* __restrict__ bias,
                                          float* __restrict__ C, int K)
{
    __shared__ float As[64][36];
    __shared__ float Bs[32][64];
    int tid = threadIdx.x;
    int m0 = blockIdx.x * 64;
    int n0 = blockIdx.y * 64;
    const float* Ab = A + (n0 / 192) * aGroupStride;
    int tx = tid & 15, ty = tid >> 4;
    float acc[4][4] = {};
    for (int kk = 0; kk < K; kk += 32) {
#pragma unroll
        for (int l = 0; l < 2; l++) {
            int f = tid + l * 256;
            int r = f >> 3, c4 = (f & 7) << 2;
            int gm = m0 + r;
            float4 v = make_float4(0.f, 0.f, 0.f, 0.f);
            if (gm < GN) v = *(const float4*)(Ab + (size_t)gm * lda + kk + c4);
            *(float4*)&As[r][c4] = v;
        }
#pragma unroll
        for (int l = 0; l < 2; l++) {
            int f = tid + l * 256;
            int r = f >> 4, c4 = (f & 15) << 2;
            *(float4*)&Bs[r][c4] = *(const float4*)(W + (size_t)(kk + r) * 384 + n0 + c4);
        }
        __syncthreads();
#pragma unroll
        for (int k = 0; k < 32; k++) {
            float a0 = As[ty * 4 + 0][k];
            float a1 = As[ty * 4 + 1][k];
            float a2 = As[ty * 4 + 2][k];
            float a3 = As[ty * 4 + 3][k];
            float4 bv = *(float4*)&Bs[k][tx * 4];
            acc[0][0] += a0 * bv.x; acc[0][1] += a0 * bv.y; acc[0][2] += a0 * bv.z; acc[0][3] += a0 * bv.w;
            acc[1][0] += a1 * bv.x; acc[1][1] += a1 * bv.y; acc[1][2] += a1 * bv.z; acc[1][3] += a1 * bv.w;
            acc[2][0] += a2 * bv.x; acc[2][1] += a2 * bv.y; acc[2][2] += a2 * bv.z; acc[2][3] += a2 * bv.w;
            acc[3][0] += a3 * bv.x; acc[3][1] += a3 * bv.y; acc[3][2] += a3 * bv.z; acc[3][3] += a3 * bv.w;
        }
        __syncthreads();
    }
#pragma unroll
    for (int i = 0; i < 4; i++) {
        int gm = m0 + ty * 4 + i;
        if (gm >= GN) continue;
#pragma unroll
        for (int j = 0; j < 4; j++)
            C[(size_t)gm * 384 + n0 + tx * 4 + j] = acc[i][j] + bias[n0 + tx * 4 + j];
    }
}

__global__ void gemm0_kernel(const float* __restrict__ x) { gemm_body(x, 128, 0, g_W0, g_B0, g_OUT0, 128); }
__global__ void gemm1_kernel() { gemm_body(g_OUT0, 384, 192, g_W1, g_B1, g_OUT1, 64); }

// ---------------- gather (segment sum via CSR), one warp per node ------------
// LAYER 0: h = relu(h_self + sum), written back in place (cols 0:64, 192:256)
// LAYER 1: fused finalize: s -> dout, xe -> g_XE, log_softmax(s) -> g_P
template <int LAYER>
__global__ void gather_layer(float* __restrict__ dout, int full)
{
    int node = blockIdx.x * 8 + (threadIdx.x >> 5);
    if (node >= GN) return;
    int lane = threadIdx.x & 31;
    float* buf = LAYER ? g_OUT1 : g_OUT0;
    float2 accp = make_float2(0.f, 0.f);
    float2 acce = make_float2(0.f, 0.f);
#pragma unroll
    for (int r = 0; r < 2; r++) {
        int beg = g_off[r][node], end = g_off[r][node + 1];
        const int* __restrict__ es = g_esrc[r];
        const float* __restrict__ ea = g_eattr[r];
        for (int k = beg; k < end; k++) {
            int src = es[k];
            float a = ea[k];
            const float* rp = buf + (size_t)src * 384;
            float2 mp = *(const float2*)(rp + 64 + r * 64 + lane * 2);
            float2 me = *(const float2*)(rp + 256 + r * 64 + lane * 2);
            accp.x += a * mp.x; accp.y += a * mp.y;
            acce.x += a * me.x; acce.y += a * me.y;
        }
    }
    float* wp = buf + (size_t)node * 384;
    float2 hp = *(const float2*)(wp + lane * 2);
    float2 he = *(const float2*)(wp + 192 + lane * 2);
    hp.x = fmaxf(hp.x + accp.x, 0.f);
    hp.y = fmaxf(hp.y + accp.y, 0.f);
    he.x = fmaxf(he.x + acce.x, 0.f);
    he.y = fmaxf(he.y + acce.y, 0.f);
    if (LAYER == 0) {
        *(float2*)(wp + lane * 2) = hp;
        *(float2*)(wp + 192 + lane * 2) = he;
    } else {
        if (full) *(float2*)(dout + 32 + (size_t)node * 64 + lane * 2) = hp;
        *(float2*)(g_XE + (size_t)node * 64 + lane * 2) = he;
        float m = fmaxf(hp.x, hp.y);
#pragma unroll
        for (int off = 16; off; off >>= 1) m = fmaxf(m, __shfl_xor_sync(0xffffffffu, m, off));
        float sum = expf(hp.x - m) + expf(hp.y - m);
#pragma unroll
        for (int off = 16; off; off >>= 1) sum += __shfl_xor_sync(0xffffffffu, sum, off);
        float lse = m + logf(sum);
        *(float2*)(g_P + (size_t)node * 64 + lane * 2) = make_float2(hp.x - lse, hp.y - lse);
    }
}

// coarsening gather: M_r[node] = sum_{edges r into node} a * P[src]
__global__ void gather_coarsen()
{
    int node = blockIdx.x * 8 + (threadIdx.x >> 5);
    if (node >= GN) return;
    int lane = threadIdx.x & 31;
    float2 acc[2];
    acc[0] = make_float2(0.f, 0.f);
    acc[1] = make_float2(0.f, 0.f);
#pragma unroll
    for (int r = 0; r < 2; r++) {
        int beg = g_off[r][node], end = g_off[r][node + 1];
        const int* __restrict__ es = g_esrc[r];
        const float* __restrict__ ea = g_eattr[r];
        for (int k = beg; k < end; k++) {
            int src = es[k];
            float a = ea[k];
            float2 p = *(const float2*)(g_P + (size_t)src * 64 + lane * 2);
            acc[r].x += a * p.x;
            acc[r].y += a * p.y;
        }
    }
    float* wp = g_M + (size_t)node * 128;
    *(float2*)(wp + lane * 2) = acc[0];
    *(float2*)(wp + 64 + lane * 2) = acc[1];
}

// ---------------- P^T @ [M0 | M1 | XE]  ->  g_CO [64 x 192] -----------------
#define PT_NB 8
__global__ void ptgemm_kernel()
{
    __shared__ float Ps[PT_NB][64];
    __shared__ float Bsr[PT_NB][192];
    int tid = threadIdx.x;
    int ag = tid & 15;  // a-rows ag*4 .. +3
    int bg = tid >> 4;  // b-cols bg*12 .. +11
    float acc[4][12] = {};
    int rpb = (GN + gridDim.x - 1) / gridDim.x;
    int r0 = blockIdx.x * rpb;
    int r1 = min(GN, r0 + rpb);
    for (int n0 = r0; n0 < r1; n0 += PT_NB) {
        __syncthreads();
#pragma unroll
        for (int l = 0; l < PT_NB; l++) {
            int i = tid + l * 256;
            int j = i >> 8, c = i & 255;
            int n = n0 + j;
            float v = 0.f;
            if (n < r1) {
                if (c < 64) v = g_P[(size_t)n * 64 + c];
                else if (c < 192) v = g_M[(size_t)n * 128 + (c - 64)];
                else v = g_XE[(size_t)n * 64 + (c - 192)];
            }
            if (c < 64) Ps[j][c] = v;
            else Bsr[j][c - 64] = v;
        }
        __syncthreads();
#pragma unroll
        for (int j = 0; j < PT_NB; j++) {
            float a[4];
#pragma unroll
            for (int i = 0; i < 4; i++) a[i] = Ps[j][ag * 4 + i];
            float b[12];
#pragma unroll
            for (int q = 0; q < 12; q++) b[q] = Bsr[j][bg * 12 + q];
#pragma unroll
            for (int i = 0; i < 4; i++)
#pragma unroll
                for (int q = 0; q < 12; q++) acc[i][q] += a[i] * b[q];
        }
    }
#pragma unroll
    for (int i = 0; i < 4; i++)
#pragma unroll
        for (int q = 0; q < 12; q++)
            atomicAdd(&g_CO[(ag * 4 + i) * 192 + bg * 12 + q], acc[i][q]);
}

// ---------------- dense 64x64 GNN + head ------------------------------------
#define DSTR 68

template <bool ACC, bool BSMEM>
__device__ __forceinline__ void dmm(float* Cs, const float* As, const float* B,
                                    const float* bias, int tid)
{
    int r0 = (tid >> 4) << 2, c0 = (tid & 15) << 2;
    float acc[4][4];
#pragma unroll
    for (int i = 0; i < 4; i++)
#pragma unroll
        for (int j = 0; j < 4; j++)
            acc[i][j] = ACC ? Cs[(r0 + i) * DSTR + c0 + j] : (bias ? bias[c0 + j] : 0.f);
#pragma unroll 8
    for (int k = 0; k < 64; k++) {
        float a[4];
#pragma unroll
        for (int i = 0; i < 4; i++) a[i] = As[(r0 + i) * DSTR + k];
        float4 bv;
        if (BSMEM) bv = *(const float4*)(B + k * DSTR + c0);
        else bv = *(const float4*)(B + k * 64 + c0);
#pragma unroll
        for (int i = 0; i < 4; i++) {
            acc[i][0] += a[i] * bv.x;
            acc[i][1] += a[i] * bv.y;
            acc[i][2] += a[i] * bv.z;
            acc[i][3] += a[i] * bv.w;
        }
    }
#pragma unroll
    for (int i = 0; i < 4; i++)
#pragma unroll
        for (int j = 0; j < 4; j++)
            Cs[(r0 + i) * DSTR + c0 + j] = acc[i][j];
}

__global__ void dense_final(const float* __restrict__ Wself0, const float* __restrict__ Wrel0,
                            const float* __restrict__ Wself1, const float* __restrict__ Wrel1,
                            const float* __restrict__ gb,
                            const float* __restrict__ lin1W, const float* __restrict__ lin1b,
                            const float* __restrict__ lin2W, const float* __restrict__ lin2b,
                            float* __restrict__ dout, int full)
{
    extern __shared__ float sm[];
    float* X = sm;
    float* A0 = X + 64 * DSTR;
    float* A1 = A0 + 64 * DSTR;
    float* H = A1 + 64 * DSTR;
    float* H2 = H + 64 * DSTR;
    float* T = H2 + 64 * DSTR;
    int tid = threadIdx.x;
    int r0 = (tid >> 4) << 2, c0 = (tid & 15) << 2;
#pragma unroll
    for (int i = 0; i < 4; i++)
#pragma unroll
        for (int j = 0; j < 4; j++) {
            int r = r0 + i, c = c0 + j;
            float xv = g_CO[r * 192 + 128 + c];
            X[r * DSTR + c] = xv;
            if (full) dout[32 + (size_t)GN * 64 + r * 64 + c] = xv;
            A0[r * DSTR + c] = g_CO[r * 192 + c];
            A1[r * DSTR + c] = g_CO[r * 192 + 64 + c];
        }
    __syncthreads();
    dmm<false, false>(H, X, Wself0, gb, tid);          // H = X@Ws0 + b0
    dmm<false, false>(T, X, Wrel0, nullptr, tid);      // T = X@Wr0[0]
    __syncthreads();
    dmm<true, true>(H, A0, T, nullptr, tid);           // H += A0@T
    __syncthreads();
    dmm<false, false>(T, X, Wrel0 + 4096, nullptr, tid);
    __syncthreads();
    dmm<true, true>(H, A1, T, nullptr, tid);
#pragma unroll
    for (int i = 0; i < 4; i++)
#pragma unroll
        for (int j = 0; j < 4; j++) {
            float* p = &H[(r0 + i) * DSTR + c0 + j];
            *p = fmaxf(*p, 0.f);
        }
    __syncthreads();
    dmm<false, false>(H2, H, Wself1, gb + 64, tid);    // H2 = H@Ws1 + b1
    dmm<false, false>(T, H, Wrel1, nullptr, tid);
    __syncthreads();
    dmm<true, true>(H2, A0, T, nullptr, tid);
    __syncthreads();
    dmm<false, false>(T, H, Wrel1 + 4096, nullptr, tid);
    __syncthreads();
    dmm<true, true>(H2, A1, T, nullptr, tid);
#pragma unroll
    for (int i = 0; i < 4; i++)
#pragma unroll
        for (int j = 0; j < 4; j++) {
            float* p = &H2[(r0 + i) * DSTR + c0 + j];
            *p = fmaxf(*p, 0.f);
        }
    __syncthreads();
    if (tid < 64) {
        float s = 0.f;
        for (int r = 0; r < 64; r++) s += H2[r * DSTR + tid];
        T[tid] = s * (1.f / 64.f); // pooled mean over rows
    }
    __syncthreads();
    if (tid < 32) {
        float h1 = lin1b[tid];
        for (int c = 0; c < 64; c++) h1 += T[c] * lin1W[c * 32 + tid];
        h1 = (h1 > 0.f) ? h1 : 0.01f * h1; // leaky_relu
        T[64 + tid] = h1;
        __syncwarp();
        float lg = lin2b[tid];
        for (int j = 0; j < 32; j++) lg += T[64 + j] * lin2W[j * 32 + tid];
        float m = lg;
#pragma unroll
        for (int off = 16; off; off >>= 1) m = fmaxf(m, __shfl_xor_sync(0xffffffffu, m, off));
        float se = expf(lg - m);
#pragma unroll
        for (int off = 16; off; off >>= 1) se += __shfl_xor_sync(0xffffffffu, se, off);
        dout[tid] = lg - m - logf(se);
    }
}

// ---------------- launcher ---------------------------------------------------
extern "C" void kernel_launch(void* const* d_in, const int* in_sizes, int n_in,
                              void* d_out, int out_size)
{
    const float* x = (const float*)d_in[0];
    // resolve edge/attr ordering by sizes (dict order vs signature order)
    int iE0 = 1, iA0 = 2, iE1 = 3, iA1 = 4;
    if (in_sizes[2] == 2 * GE) { iE0 = 1; iE1 = 2; iA0 = 3; iA1 = 4; }
    const int* e0 = (const int*)d_in[iE0];
    const float* a0 = (const float*)d_in[iA0];
    const int* e1 = (const int*)d_in[iE1];
    const float* a1 = (const float*)d_in[iA1];
    const float* W[19];
    for (int i = 0; i < 19; i++) W[i] = (const float*)d_in[5 + i];
    int full = (out_size >= 32 + GN * 64 + 64 * 64) ? 1 : 0;
    float* dout = (float*)d_out;

    cudaFuncSetAttribute(dense_final, cudaFuncAttributeMaxDynamicSharedMemorySize,
                         6 * 64 * DSTR * (int)sizeof(float));

    pack_weights<<<192, 256>>>(W[0], W[1], W[2], W[3], W[4], W[5], W[6], W[7], W[8], W[9]);
    zero_small<<<205, 256>>>();
    hist_kernel<<<2500, 256>>>(e0, e1);
    scan_kernel<<<2, 1024>>>();
    place_kernel<<<2500, 256>>>(e0, a0, e1, a1);
    gemm0_kernel<<<dim3(313, 6), 256>>>(x);
    gather_layer<0><<<2500, 256>>>(dout, full);
    gemm1_kernel<<<dim3(313, 6), 256>>>();
    gather_layer<1><<<2500, 256>>>(dout, full);
    gather_coarsen<<<2500, 256>>>();
    ptgemm_kernel<<<160, 256>>>();
    dense_final<<<1, 256, 6 * 64 * DSTR * sizeof(float)>>>(
        W[10], W[11], W[12], W[13], W[14], W[15], W[16], W[17], W[18], dout, full);
}